// round 9
// baseline (speedup 1.0000x reference)
#include <cuda_runtime.h>
#include <cuda_bf16.h>
#include <cstdint>

// Problem dims
#define BATCH   8
#define SEQ     2048
#define DIN     1024
#define DHEAD   64
#define BS_TOT  (BATCH * SEQ)       // 16384

// Projected q/k/v as split bf16 pairs (val = hi + lo), q pre-scaled by 0.125.
__device__ __nv_bfloat16 g_qh[BS_TOT * DHEAD];
__device__ __nv_bfloat16 g_ql[BS_TOT * DHEAD];
__device__ __nv_bfloat16 g_kh[BS_TOT * DHEAD];
__device__ __nv_bfloat16 g_kl[BS_TOT * DHEAD];
__device__ __nv_bfloat16 g_vh[BS_TOT * DHEAD];
__device__ __nv_bfloat16 g_vl[BS_TOT * DHEAD];

// W (q|k|v concatenated, [k][192]) pre-split to bf16 hi/lo once per launch.
__device__ __nv_bfloat16 g_wh[DIN * 192];
__device__ __nv_bfloat16 g_wl[DIN * 192];

// ---------------------------------------------------------------------------
// PTX helpers (sm_80-era; compile fine at compute_100)
// ---------------------------------------------------------------------------
__device__ __forceinline__ uint32_t smem_u32(const void* p) {
    uint32_t a;
    asm("{ .reg .u64 t; cvta.to.shared.u64 t, %1; cvt.u32.u64 %0, t; }" : "=r"(a) : "l"(p));
    return a;
}
__device__ __forceinline__ void mma16816(float* d, const uint32_t* a,
                                         uint32_t b0, uint32_t b1) {
    asm volatile(
        "mma.sync.aligned.m16n8k16.row.col.f32.bf16.bf16.f32 "
        "{%0,%1,%2,%3}, {%4,%5,%6,%7}, {%8,%9}, {%0,%1,%2,%3};\n"
        : "+f"(d[0]), "+f"(d[1]), "+f"(d[2]), "+f"(d[3])
        : "r"(a[0]), "r"(a[1]), "r"(a[2]), "r"(a[3]), "r"(b0), "r"(b1));
}
__device__ __forceinline__ void ldmx4(uint32_t* r, uint32_t addr) {
    asm volatile("ldmatrix.sync.aligned.m8n8.x4.shared.b16 {%0,%1,%2,%3}, [%4];"
                 : "=r"(r[0]), "=r"(r[1]), "=r"(r[2]), "=r"(r[3]) : "r"(addr));
}
__device__ __forceinline__ void ldmx2t(uint32_t& r0, uint32_t& r1, uint32_t addr) {
    asm volatile("ldmatrix.sync.aligned.m8n8.x2.trans.shared.b16 {%0,%1}, [%2];"
                 : "=r"(r0), "=r"(r1) : "r"(addr));
}
__device__ __forceinline__ void cp16(uint32_t dst, const void* src) {
    asm volatile("cp.async.ca.shared.global [%0], [%1], 16;" :: "r"(dst), "l"(src));
}
__device__ __forceinline__ void cp_commit() {
    asm volatile("cp.async.commit_group;");
}
template <int N> __device__ __forceinline__ void cp_wait() {
    asm volatile("cp.async.wait_group %0;" :: "n"(N));
}
__device__ __forceinline__ uint32_t pack2(float a, float b) {
    __nv_bfloat162 h = __floats2bfloat162_rn(a, b);   // a -> lower 16 bits
    return *(uint32_t*)&h;
}
__device__ __forceinline__ void split4(float4 v, uint2& hi, uint2& lo) {
    uint32_t h01 = pack2(v.x, v.y), h23 = pack2(v.z, v.w);
    float2 f01 = __bfloat1622float2(*(__nv_bfloat162*)&h01);
    float2 f23 = __bfloat1622float2(*(__nv_bfloat162*)&h23);
    hi.x = h01; hi.y = h23;
    lo.x = pack2(v.x - f01.x, v.y - f01.y);
    lo.y = pack2(v.z - f23.x, v.w - f23.y);
}

// ===========================================================================
// W pre-split: [1024][192] fp32 (q|k|v) -> bf16 hi/lo. (unchanged, proven)
// ===========================================================================
__global__ __launch_bounds__(256) void wsplit_kernel(
    const float* __restrict__ Wq, const float* __restrict__ Wk,
    const float* __restrict__ Wv)
{
    int i  = blockIdx.x * 256 + threadIdx.x;   // 0..49151
    int k  = i / 48;
    int c4 = (i % 48) * 4;                     // 0..188 step 4
    int arr = c4 >> 6;
    int cc  = c4 & 63;
    const float* W = (arr == 0) ? Wq : (arr == 1) ? Wk : Wv;
    float4 v = *(const float4*)&W[k * DHEAD + cc];
    uint2 hi, lo; split4(v, hi, lo);
    *(uint2*)&g_wh[k * 192 + c4] = hi;
    *(uint2*)&g_wl[k * 192 + c4] = lo;
}

// ===========================================================================
// Fused QKV projection (unchanged, proven ~75us in R8).
// ===========================================================================
#define XP   72
#define WPIT 200
#define QKV_XH 0
#define QKV_XL 4608
#define QKV_WH 9216
#define QKV_WL 22016
#define QKV_SMEM_BYTES ((22016 + 12800) * 2)   // 69632

__global__ __launch_bounds__(128, 2) void qkv_kernel(
    const float* __restrict__ x,
    const float* __restrict__ bq, const float* __restrict__ bk,
    const float* __restrict__ bv)
{
    extern __shared__ __nv_bfloat16 smq[];
    const uint32_t sbase = smem_u32(smq);

    const int t    = threadIdx.x;
    const int w    = t >> 5;
    const int lane = t & 31;
    const int g    = lane >> 2;
    const int qc   = lane & 3;
    const int m0   = blockIdx.x * 64;
    const int wm   = w * 16;

    float acc[24][4];
#pragma unroll
    for (int f = 0; f < 24; f++)
#pragma unroll
        for (int j = 0; j < 4; j++) acc[f][j] = 0.0f;

    const int srow = t >> 1;

    for (int k0 = 0; k0 < DIN; k0 += 64) {
#pragma unroll
        for (int j = 0; j < 12; j++) {
            int i   = t + j * 128;
            int r   = i / 24;
            int seg = (i % 24) * 8;
            const int go = (k0 + r) * 192 + seg;
            cp16(sbase + (uint32_t)(QKV_WH + r * WPIT + seg) * 2, g_wh + go);
            cp16(sbase + (uint32_t)(QKV_WL + r * WPIT + seg) * 2, g_wl + go);
        }
        cp_commit();

        {
            int ks = (t & 1) * 32;
            const float* xr = &x[(m0 + srow) * DIN + k0 + ks];
#pragma unroll
            for (int j = 0; j < 8; j++) {
                float4 v4 = *(const float4*)&xr[j * 4];
                uint2 hi, lo; split4(v4, hi, lo);
                int eo = srow * XP + ks + j * 4;
                *(uint2*)&smq[QKV_XH + eo] = hi;
                *(uint2*)&smq[QKV_XL + eo] = lo;
            }
        }
        cp_wait<0>();
        __syncthreads();

        uint32_t ah[4][4], al[4][4];
        const int ar = wm + (lane & 7) + ((lane >> 3) & 1) * 8;
#pragma unroll
        for (int k4 = 0; k4 < 4; k4++) {
            int ac = k4 * 16 + (lane >> 4) * 8;
            ldmx4(ah[k4], sbase + (uint32_t)(QKV_XH + ar * XP + ac) * 2);
            ldmx4(al[k4], sbase + (uint32_t)(QKV_XL + ar * XP + ac) * 2);
        }

#pragma unroll
        for (int f = 0; f < 24; f++) {
#pragma unroll
            for (int k4 = 0; k4 < 4; k4++) {
                int krow = k4 * 16 + (lane & 15);
                uint32_t baddr = (uint32_t)(krow * WPIT + f * 8) * 2;
                uint32_t bh0, bh1, bl0, bl1;
                ldmx2t(bh0, bh1, sbase + (uint32_t)QKV_WH * 2 + baddr);
                ldmx2t(bl0, bl1, sbase + (uint32_t)QKV_WL * 2 + baddr);
                mma16816(acc[f], ah[k4], bh0, bh1);
                mma16816(acc[f], ah[k4], bl0, bl1);
                mma16816(acc[f], al[k4], bh0, bh1);
            }
        }
        __syncthreads();
    }

    const int rl = m0 + wm + g;
    const int rh = rl + 8;
#pragma unroll
    for (int f = 0; f < 24; f++) {
        int c   = f * 8 + 2 * qc;
        int arr = c >> 6;
        int cc  = c & 63;
        const float* ba = (arr == 0) ? bq : (arr == 1) ? bk : bv;
        __nv_bfloat16* oh = (arr == 0) ? g_qh : (arr == 1) ? g_kh : g_vh;
        __nv_bfloat16* ol = (arr == 0) ? g_ql : (arr == 1) ? g_kl : g_vl;
        float s  = (arr == 0) ? 0.125f : 1.0f;
        float b0 = ba[cc], b1 = ba[cc + 1];
        float v0 = (acc[f][0] + b0) * s, v1 = (acc[f][1] + b1) * s;
        float v2 = (acc[f][2] + b0) * s, v3 = (acc[f][3] + b1) * s;
        uint32_t h01 = pack2(v0, v1);
        uint32_t h23 = pack2(v2, v3);
        float2 f01 = __bfloat1622float2(*(__nv_bfloat162*)&h01);
        float2 f23 = __bfloat1622float2(*(__nv_bfloat162*)&h23);
        *(uint32_t*)&oh[rl * DHEAD + cc] = h01;
        *(uint32_t*)&ol[rl * DHEAD + cc] = pack2(v0 - f01.x, v1 - f01.y);
        *(uint32_t*)&oh[rh * DHEAD + cc] = h23;
        *(uint32_t*)&ol[rh * DHEAD + cc] = pack2(v2 - f23.x, v3 - f23.y);
    }
}

// ===========================================================================
// Flash attention — ONE change vs R8: Br 128->64, 128 thr/CTA, 3 CTAs/SM.
// Per-warp inner loops byte-identical to the proven R6/R8 version
// (direct-LDS K B-frags, ldmx2t V B-frags, same softmax).
// grid (32, 8); staging rep count 2->4 (128 threads stage the same 512
// 16B-chunks per array).
// ===========================================================================
#define KP 72
#define TILE_ELEMS (64 * KP)               // 4608
#define ABASE(arr, buf) (((arr) * 2 + (buf)) * TILE_ELEMS)
#define ATTN_SMEM_BYTES (8 * TILE_ELEMS * 2)   // 73728

__global__ __launch_bounds__(128, 3) void attn_kernel(float* __restrict__ out)
{
    extern __shared__ __nv_bfloat16 sma[];
    const uint32_t sbase = smem_u32(sma);

    const int t    = threadIdx.x;
    const int w    = t >> 5;               // 0..3
    const int lane = t & 31;
    const int g    = lane >> 2;
    const int qc   = lane & 3;

    const int qt = blockIdx.x;             // 0..31
    const int b  = blockIdx.y;             // 0..7
    const int qrow0  = b * SEQ + qt * 64;
    const int kvbase = b * SEQ;

    const int rlo = qrow0 + 16 * w + g;
    const int rhi = rlo + 8;

    const __nv_bfloat16* gsrc[4] = {g_kh, g_kl, g_vh, g_vl};

    // issue tile 0 loads into buf 0
#pragma unroll
    for (int arr = 0; arr < 4; arr++) {
#pragma unroll
        for (int rep = 0; rep < 4; rep++) {
            int i   = t + rep * 128;       // 0..511
            int r   = i >> 3;
            int seg = (i & 7) * 8;
            cp16(sbase + (uint32_t)(ABASE(arr, 0) + r * KP + seg) * 2,
                 gsrc[arr] + (kvbase + r) * DHEAD + seg);
        }
    }
    cp_commit();

    // ---- Q fragments once (warp-invariant across KV tiles) ----
    uint32_t qh[4][4], ql[4][4];
#pragma unroll
    for (int k4 = 0; k4 < 4; k4++) {
        int c = k4 * 16 + qc * 2;
        qh[k4][0] = *(const uint32_t*)&g_qh[rlo * DHEAD + c];
        qh[k4][1] = *(const uint32_t*)&g_qh[rhi * DHEAD + c];
        qh[k4][2] = *(const uint32_t*)&g_qh[rlo * DHEAD + c + 8];
        qh[k4][3] = *(const uint32_t*)&g_qh[rhi * DHEAD + c + 8];
        ql[k4][0] = *(const uint32_t*)&g_ql[rlo * DHEAD + c];
        ql[k4][1] = *(const uint32_t*)&g_ql[rhi * DHEAD + c];
        ql[k4][2] = *(const uint32_t*)&g_ql[rlo * DHEAD + c + 8];
        ql[k4][3] = *(const uint32_t*)&g_ql[rhi * DHEAD + c + 8];
    }

    float m_lo = -3.0e38f, m_hi = -3.0e38f, l_lo = 0.0f, l_hi = 0.0f;
    float oacc[8][4];
#pragma unroll
    for (int n = 0; n < 8; n++)
#pragma unroll
        for (int j = 0; j < 4; j++) oacc[n][j] = 0.0f;

    for (int kt = 0; kt < SEQ / 64; kt++) {
        const int buf = kt & 1;

        // prefetch next tile into the other buffer
        if (kt < SEQ / 64 - 1) {
            const int nb = buf ^ 1;
            const int krow0 = kvbase + (kt + 1) * 64;
#pragma unroll
            for (int arr = 0; arr < 4; arr++) {
#pragma unroll
                for (int rep = 0; rep < 4; rep++) {
                    int i   = t + rep * 128;
                    int r   = i >> 3;
                    int seg = (i & 7) * 8;
                    cp16(sbase + (uint32_t)(ABASE(arr, nb) + r * KP + seg) * 2,
                         gsrc[arr] + (krow0 + r) * DHEAD + seg);
                }
            }
            cp_commit();
            cp_wait<1>();
        } else {
            cp_wait<0>();
        }
        __syncthreads();

        const __nv_bfloat16* Kh = sma + ABASE(0, buf);
        const __nv_bfloat16* Kl = sma + ABASE(1, buf);
        const uint32_t vh_b = sbase + (uint32_t)ABASE(2, buf) * 2;
        const uint32_t vl_b = sbase + (uint32_t)ABASE(3, buf) * 2;

        // ---- S = Q K^T (3-pass split) ----
        float sacc[8][4];
#pragma unroll
        for (int n = 0; n < 8; n++)
#pragma unroll
            for (int j = 0; j < 4; j++) sacc[n][j] = 0.0f;

#pragma unroll
        for (int k4 = 0; k4 < 4; k4++) {
#pragma unroll
            for (int n = 0; n < 8; n++) {
                int base = (n * 8 + g) * KP + k4 * 16 + qc * 2;
                uint32_t bh0 = *(const uint32_t*)&Kh[base];
                uint32_t bh1 = *(const uint32_t*)&Kh[base + 8];
                uint32_t bl0 = *(const uint32_t*)&Kl[base];
                uint32_t bl1 = *(const uint32_t*)&Kl[base + 8];
                mma16816(sacc[n], qh[k4], bh0, bh1);
                mma16816(sacc[n], qh[k4], bl0, bl1);
                mma16816(sacc[n], ql[k4], bh0, bh1);
            }
        }

        // ---- online softmax (rows rlo: c0/c1, rhi: c2/c3) ----
        float tl = -3.0e38f, th = -3.0e38f;
#pragma unroll
        for (int n = 0; n < 8; n++) {
            tl = fmaxf(tl, fmaxf(sacc[n][0], sacc[n][1]));
            th = fmaxf(th, fmaxf(sacc[n][2], sacc[n][3]));
        }
        tl = fmaxf(tl, __shfl_xor_sync(0xffffffffu, tl, 1));
        tl = fmaxf(tl, __shfl_xor_sync(0xffffffffu, tl, 2));
        th = fmaxf(th, __shfl_xor_sync(0xffffffffu, th, 1));
        th = fmaxf(th, __shfl_xor_sync(0xffffffffu, th, 2));

        float mn_lo = fmaxf(m_lo, tl);
        float mn_hi = fmaxf(m_hi, th);
        float al_lo = __expf(m_lo - mn_lo);
        float al_hi = __expf(m_hi - mn_hi);
        m_lo = mn_lo; m_hi = mn_hi;

        float slo = 0.0f, shi = 0.0f;
#pragma unroll
        for (int n = 0; n < 8; n++) {
            float e0 = __expf(sacc[n][0] - mn_lo);
            float e1 = __expf(sacc[n][1] - mn_lo);
            float e2 = __expf(sacc[n][2] - mn_hi);
            float e3 = __expf(sacc[n][3] - mn_hi);
            sacc[n][0] = e0; sacc[n][1] = e1; sacc[n][2] = e2; sacc[n][3] = e3;
            slo += e0 + e1; shi += e2 + e3;
        }
        slo += __shfl_xor_sync(0xffffffffu, slo, 1);
        slo += __shfl_xor_sync(0xffffffffu, slo, 2);
        shi += __shfl_xor_sync(0xffffffffu, shi, 1);
        shi += __shfl_xor_sync(0xffffffffu, shi, 2);
        l_lo = l_lo * al_lo + slo;
        l_hi = l_hi * al_hi + shi;

#pragma unroll
        for (int n = 0; n < 8; n++) {
            oacc[n][0] *= al_lo; oacc[n][1] *= al_lo;
            oacc[n][2] *= al_hi; oacc[n][3] *= al_hi;
        }

        // ---- PV: O += P V (P frags in regs; V B-frags via ldmatrix.trans) ----
#pragma unroll
        for (int pk = 0; pk < 4; pk++) {
            uint32_t pah[4], pal[4];
#pragma unroll
            for (int half = 0; half < 2; half++) {
                float e0 = sacc[2 * pk + half][0];
                float e1 = sacc[2 * pk + half][1];
                float e2 = sacc[2 * pk + half][2];
                float e3 = sacc[2 * pk + half][3];
                uint32_t h01 = pack2(e0, e1);
                uint32_t h23 = pack2(e2, e3);
                float2 f01 = __bfloat1622float2(*(__nv_bfloat162*)&h01);
                float2 f23 = __bfloat1622float2(*(__nv_bfloat162*)&h23);
                pah[0 + 2 * half] = h01;
                pah[1 + 2 * half] = h23;
                pal[0 + 2 * half] = pack2(e0 - f01.x, e1 - f01.y);
                pal[1 + 2 * half] = pack2(e2 - f23.x, e3 - f23.y);
            }
            const uint32_t krow = (uint32_t)(pk * 16 + (lane & 15));
#pragma unroll
            for (int n = 0; n < 8; n++) {
                uint32_t off = (krow * KP + n * 8) * 2;
                uint32_t bh0, bh1, bl0, bl1;
                ldmx2t(bh0, bh1, vh_b + off);
                ldmx2t(bl0, bl1, vl_b + off);
                mma16816(oacc[n], pah, bh0, bh1);
                mma16816(oacc[n], pah, bl0, bl1);
                mma16816(oacc[n], pal, bh0, bh1);
            }
        }
        __syncthreads();   // compute done before next prefetch overwrites buf^1
    }

    // ---- epilogue: normalize + store fp32 ----
    const float il = 1.0f / l_lo;
    const float ih = 1.0f / l_hi;
#pragma unroll
    for (int n = 0; n < 8; n++) {
        int c = n * 8 + qc * 2;
        float2 v0 = make_float2(oacc[n][0] * il, oacc[n][1] * il);
        float2 v1 = make_float2(oacc[n][2] * ih, oacc[n][3] * ih);
        *(float2*)&out[rlo * DHEAD + c] = v0;
        *(float2*)&out[rhi * DHEAD + c] = v1;
    }
}

// ===========================================================================
extern "C" void kernel_launch(void* const* d_in, const int* in_sizes, int n_in,
                              void* d_out, int out_size)
{
    const float* x  = (const float*)d_in[0];
    const float* Wq = (const float*)d_in[1];
    const float* bq = (const float*)d_in[2];
    const float* Wk = (const float*)d_in[3];
    const float* bk = (const float*)d_in[4];
    const float* Wv = (const float*)d_in[5];
    const float* bv = (const float*)d_in[6];
    float* out = (float*)d_out;

    (void)in_sizes; (void)n_in; (void)out_size;

    cudaFuncSetAttribute(qkv_kernel,
                         cudaFuncAttributeMaxDynamicSharedMemorySize, QKV_SMEM_BYTES);
    cudaFuncSetAttribute(attn_kernel,
                         cudaFuncAttributeMaxDynamicSharedMemorySize, ATTN_SMEM_BYTES);

    wsplit_kernel<<<192, 256>>>(Wq, Wk, Wv);
    qkv_kernel<<<dim3(BS_TOT / 64), 128, QKV_SMEM_BYTES>>>(x, bq, bk, bv);
    attn_kernel<<<dim3(SEQ / 64, BATCH), 128, ATTN_SMEM_BYTES>>>(out);
}

// round 14
// speedup vs baseline: 1.9166x; 1.9166x over previous
#include <cuda_runtime.h>
#include <cuda_fp16.h>
#include <cstdint>

// Problem dims
#define BATCH   8
#define SEQ     2048
#define DIN     1024
#define DHEAD   64
#define BS_TOT  (BATCH * SEQ)       // 16384

// Projected q/k/v as fp16 (single precision-pass), q pre-scaled by 0.125.
__device__ __half g_q[BS_TOT * DHEAD];
__device__ __half g_k[BS_TOT * DHEAD];
__device__ __half g_v[BS_TOT * DHEAD];

// W (q|k|v concatenated, [k][192]) pre-converted to fp16 once per launch.
__device__ __half g_w[DIN * 192];

// ---------------------------------------------------------------------------
// PTX helpers (sm_80-era; compile fine at compute_100)
// ---------------------------------------------------------------------------
__device__ __forceinline__ uint32_t smem_u32(const void* p) {
    uint32_t a;
    asm("{ .reg .u64 t; cvta.to.shared.u64 t, %1; cvt.u32.u64 %0, t; }" : "=r"(a) : "l"(p));
    return a;
}
__device__ __forceinline__ void mma16816(float* d, const uint32_t* a,
                                         uint32_t b0, uint32_t b1) {
    asm volatile(
        "mma.sync.aligned.m16n8k16.row.col.f32.f16.f16.f32 "
        "{%0,%1,%2,%3}, {%4,%5,%6,%7}, {%8,%9}, {%0,%1,%2,%3};\n"
        : "+f"(d[0]), "+f"(d[1]), "+f"(d[2]), "+f"(d[3])
        : "r"(a[0]), "r"(a[1]), "r"(a[2]), "r"(a[3]), "r"(b0), "r"(b1));
}
__device__ __forceinline__ void ldmx4(uint32_t* r, uint32_t addr) {
    asm volatile("ldmatrix.sync.aligned.m8n8.x4.shared.b16 {%0,%1,%2,%3}, [%4];"
                 : "=r"(r[0]), "=r"(r[1]), "=r"(r[2]), "=r"(r[3]) : "r"(addr));
}
__device__ __forceinline__ void ldmx2t(uint32_t& r0, uint32_t& r1, uint32_t addr) {
    asm volatile("ldmatrix.sync.aligned.m8n8.x2.trans.shared.b16 {%0,%1}, [%2];"
                 : "=r"(r0), "=r"(r1) : "r"(addr));
}
__device__ __forceinline__ void cp16(uint32_t dst, const void* src) {
    asm volatile("cp.async.ca.shared.global [%0], [%1], 16;" :: "r"(dst), "l"(src));
}
__device__ __forceinline__ void cp_commit() {
    asm volatile("cp.async.commit_group;");
}
template <int N> __device__ __forceinline__ void cp_wait() {
    asm volatile("cp.async.wait_group %0;" :: "n"(N));
}
__device__ __forceinline__ uint32_t pack2h(float a, float b) {
    __half2 h = __floats2half2_rn(a, b);   // a -> lower 16 bits
    return *(uint32_t*)&h;
}
__device__ __forceinline__ uint2 cvt4h(float4 v) {
    return make_uint2(pack2h(v.x, v.y), pack2h(v.z, v.w));
}

// ===========================================================================
// W pre-convert: [1024][192] fp32 (q|k|v) -> fp16. 192 blocks x 256 thr.
// ===========================================================================
__global__ __launch_bounds__(256) void wsplit_kernel(
    const float* __restrict__ Wq, const float* __restrict__ Wk,
    const float* __restrict__ Wv)
{
    int i  = blockIdx.x * 256 + threadIdx.x;   // 0..49151
    int k  = i / 48;
    int c4 = (i % 48) * 4;                     // 0..188 step 4
    int arr = c4 >> 6;
    int cc  = c4 & 63;
    const float* W = (arr == 0) ? Wq : (arr == 1) ? Wk : Wv;
    float4 v = *(const float4*)&W[k * DHEAD + cc];
    *(uint2*)&g_w[k * 192 + c4] = cvt4h(v);
}

// ===========================================================================
// Fused QKV projection (mma.sync fp16 single-pass).
// 256 CTAs x 128 thr; 64 rows/CTA; warp w: rows 16w..16w+15, all 192 cols.
// ===========================================================================
#define XP   72
#define WPIT 200
#define QKV_XF 0
#define QKV_WF 4608                     // 64*72
#define QKV_SMEM_BYTES ((4608 + 12800) * 2)   // 34816

__global__ __launch_bounds__(128, 3) void qkv_kernel(
    const float* __restrict__ x,
    const float* __restrict__ bq, const float* __restrict__ bk,
    const float* __restrict__ bv)
{
    extern __shared__ __half smq[];
    const uint32_t sbase = smem_u32(smq);

    const int t    = threadIdx.x;
    const int w    = t >> 5;
    const int lane = t & 31;
    const int g    = lane >> 2;
    const int qc   = lane & 3;
    const int m0   = blockIdx.x * 64;
    const int wm   = w * 16;

    float acc[24][4];
#pragma unroll
    for (int f = 0; f < 24; f++)
#pragma unroll
        for (int j = 0; j < 4; j++) acc[f][j] = 0.0f;

    const int srow = t >> 1;

    for (int k0 = 0; k0 < DIN; k0 += 64) {
        // ---- issue W chunk cp.async (pre-converted fp16) ----
#pragma unroll
        for (int j = 0; j < 12; j++) {
            int i   = t + j * 128;               // 0..1535
            int r   = i / 24;                    // 0..63
            int seg = (i % 24) * 8;              // 0..184
            cp16(sbase + (uint32_t)(QKV_WF + r * WPIT + seg) * 2,
                 g_w + (k0 + r) * 192 + seg);
        }
        cp_commit();

        // ---- stage X chunk [64 rows x 64 k] fp16 (overlaps cp latency) ----
        {
            int ks = (t & 1) * 32;
            const float* xr = &x[(m0 + srow) * DIN + k0 + ks];
#pragma unroll
            for (int j = 0; j < 8; j++) {
                float4 v4 = *(const float4*)&xr[j * 4];
                *(uint2*)&smq[QKV_XF + srow * XP + ks + j * 4] = cvt4h(v4);
            }
        }
        cp_wait<0>();
        __syncthreads();

        // ---- A-frags for all 4 k-tiles ----
        uint32_t af[4][4];
        const int ar = wm + (lane & 7) + ((lane >> 3) & 1) * 8;
#pragma unroll
        for (int k4 = 0; k4 < 4; k4++) {
            int ac = k4 * 16 + (lane >> 4) * 8;
            ldmx4(af[k4], sbase + (uint32_t)(QKV_XF + ar * XP + ac) * 2);
        }

        // ---- per fragment: 4 ldmx2t + 4 MMAs ----
#pragma unroll
        for (int f = 0; f < 24; f++) {
#pragma unroll
            for (int k4 = 0; k4 < 4; k4++) {
                int krow = k4 * 16 + (lane & 15);
                uint32_t baddr = (uint32_t)(QKV_WF + krow * WPIT + f * 8) * 2;
                uint32_t b0, b1;
                ldmx2t(b0, b1, sbase + baddr);
                mma16816(acc[f], af[k4], b0, b1);
            }
        }
        __syncthreads();
    }

    // ---- epilogue: bias + scale, convert fp16, store ----
    const int rl = m0 + wm + g;
    const int rh = rl + 8;
#pragma unroll
    for (int f = 0; f < 24; f++) {
        int c   = f * 8 + 2 * qc;
        int arr = c >> 6;
        int cc  = c & 63;
        const float* ba = (arr == 0) ? bq : (arr == 1) ? bk : bv;
        __half* op = (arr == 0) ? g_q : (arr == 1) ? g_k : g_v;
        float s  = (arr == 0) ? 0.125f : 1.0f;
        float b0 = ba[cc], b1 = ba[cc + 1];
        *(uint32_t*)&op[rl * DHEAD + cc] =
            pack2h((acc[f][0] + b0) * s, (acc[f][1] + b1) * s);
        *(uint32_t*)&op[rh * DHEAD + cc] =
            pack2h((acc[f][2] + b0) * s, (acc[f][3] + b1) * s);
    }
}

// ===========================================================================
// Flash attention — R8 proven structure (Br=128, 256 thr, 8 warps),
// fp16 single-pass (1 MMA where the split version had 3).
// Plain __launch_bounds__(256) as in the R8 passing build; 2 CTAs/SM from
// smem 36.9KB + ~110 regs.
// ===========================================================================
#define KP 72
#define TILE_ELEMS (64 * KP)               // 4608
#define ABASE(arr, buf) (((arr) * 2 + (buf)) * TILE_ELEMS)
#define ATTN_SMEM_BYTES (4 * TILE_ELEMS * 2)   // 36864

__global__ __launch_bounds__(256) void attn_kernel(float* __restrict__ out)
{
    extern __shared__ __half sma[];
    const uint32_t sbase = smem_u32(sma);

    const int t    = threadIdx.x;
    const int w    = t >> 5;
    const int lane = t & 31;
    const int g    = lane >> 2;
    const int qc   = lane & 3;

    const int qt = blockIdx.x;             // 0..15
    const int b  = blockIdx.y;             // 0..7
    const int qrow0  = b * SEQ + qt * 128;
    const int kvbase = b * SEQ;

    const int rlo = qrow0 + 16 * w + g;
    const int rhi = rlo + 8;

    const __half* gsrc[2] = {g_k, g_v};

    // issue tile 0 loads into buf 0
#pragma unroll
    for (int arr = 0; arr < 2; arr++) {
#pragma unroll
        for (int rep = 0; rep < 2; rep++) {
            int i   = t + rep * 256;       // 0..511
            int r   = i >> 3;
            int seg = (i & 7) * 8;
            cp16(sbase + (uint32_t)(ABASE(arr, 0) + r * KP + seg) * 2,
                 gsrc[arr] + (kvbase + r) * DHEAD + seg);
        }
    }
    cp_commit();

    // ---- Q fragments once (warp-invariant across KV tiles) ----
    uint32_t qf[4][4];
#pragma unroll
    for (int k4 = 0; k4 < 4; k4++) {
        int c = k4 * 16 + qc * 2;
        qf[k4][0] = *(const uint32_t*)&g_q[rlo * DHEAD + c];
        qf[k4][1] = *(const uint32_t*)&g_q[rhi * DHEAD + c];
        qf[k4][2] = *(const uint32_t*)&g_q[rlo * DHEAD + c + 8];
        qf[k4][3] = *(const uint32_t*)&g_q[rhi * DHEAD + c + 8];
    }

    float m_lo = -3.0e38f, m_hi = -3.0e38f, l_lo = 0.0f, l_hi = 0.0f;
    float oacc[8][4];
#pragma unroll
    for (int n = 0; n < 8; n++)
#pragma unroll
        for (int j = 0; j < 4; j++) oacc[n][j] = 0.0f;

    for (int kt = 0; kt < SEQ / 64; kt++) {
        const int buf = kt & 1;

        // prefetch next tile into the other buffer
        if (kt < SEQ / 64 - 1) {
            const int nb = buf ^ 1;
            const int krow0 = kvbase + (kt + 1) * 64;
#pragma unroll
            for (int arr = 0; arr < 2; arr++) {
#pragma unroll
                for (int rep = 0; rep < 2; rep++) {
                    int i   = t + rep * 256;
                    int r   = i >> 3;
                    int seg = (i & 7) * 8;
                    cp16(sbase + (uint32_t)(ABASE(arr, nb) + r * KP + seg) * 2,
                         gsrc[arr] + (krow0 + r) * DHEAD + seg);
                }
            }
            cp_commit();
            cp_wait<1>();
        } else {
            cp_wait<0>();
        }
        __syncthreads();

        const __half* Kf = sma + ABASE(0, buf);
        const uint32_t v_b = sbase + (uint32_t)ABASE(1, buf) * 2;

        // ---- S = Q K^T (single pass) ----
        float sacc[8][4];
#pragma unroll
        for (int n = 0; n < 8; n++)
#pragma unroll
            for (int j = 0; j < 4; j++) sacc[n][j] = 0.0f;

#pragma unroll
        for (int k4 = 0; k4 < 4; k4++) {
#pragma unroll
            for (int n = 0; n < 8; n++) {
                int base = (n * 8 + g) * KP + k4 * 16 + qc * 2;
                uint32_t b0 = *(const uint32_t*)&Kf[base];
                uint32_t b1 = *(const uint32_t*)&Kf[base + 8];
                mma16816(sacc[n], qf[k4], b0, b1);
            }
        }

        // ---- online softmax (rows rlo: c0/c1, rhi: c2/c3) ----
        float tl = -3.0e38f, th = -3.0e38f;
#pragma unroll
        for (int n = 0; n < 8; n++) {
            tl = fmaxf(tl, fmaxf(sacc[n][0], sacc[n][1]));
            th = fmaxf(th, fmaxf(sacc[n][2], sacc[n][3]));
        }
        tl = fmaxf(tl, __shfl_xor_sync(0xffffffffu, tl, 1));
        tl = fmaxf(tl, __shfl_xor_sync(0xffffffffu, tl, 2));
        th = fmaxf(th, __shfl_xor_sync(0xffffffffu, th, 1));
        th = fmaxf(th, __shfl_xor_sync(0xffffffffu, th, 2));

        float mn_lo = fmaxf(m_lo, tl);
        float mn_hi = fmaxf(m_hi, th);
        float al_lo = __expf(m_lo - mn_lo);
        float al_hi = __expf(m_hi - mn_hi);
        m_lo = mn_lo; m_hi = mn_hi;

        float slo = 0.0f, shi = 0.0f;
#pragma unroll
        for (int n = 0; n < 8; n++) {
            float e0 = __expf(sacc[n][0] - mn_lo);
            float e1 = __expf(sacc[n][1] - mn_lo);
            float e2 = __expf(sacc[n][2] - mn_hi);
            float e3 = __expf(sacc[n][3] - mn_hi);
            sacc[n][0] = e0; sacc[n][1] = e1; sacc[n][2] = e2; sacc[n][3] = e3;
            slo += e0 + e1; shi += e2 + e3;
        }
        slo += __shfl_xor_sync(0xffffffffu, slo, 1);
        slo += __shfl_xor_sync(0xffffffffu, slo, 2);
        shi += __shfl_xor_sync(0xffffffffu, shi, 1);
        shi += __shfl_xor_sync(0xffffffffu, shi, 2);
        l_lo = l_lo * al_lo + slo;
        l_hi = l_hi * al_hi + shi;

#pragma unroll
        for (int n = 0; n < 8; n++) {
            oacc[n][0] *= al_lo; oacc[n][1] *= al_lo;
            oacc[n][2] *= al_hi; oacc[n][3] *= al_hi;
        }

        // ---- PV: O += P V (P frags in regs; V B-frags via ldmatrix.trans) ----
#pragma unroll
        for (int pk = 0; pk < 4; pk++) {
            uint32_t pa[4];
#pragma unroll
            for (int half = 0; half < 2; half++) {
                pa[0 + 2 * half] = pack2h(sacc[2 * pk + half][0],
                                          sacc[2 * pk + half][1]);
                pa[1 + 2 * half] = pack2h(sacc[2 * pk + half][2],
                                          sacc[2 * pk + half][3]);
            }
            const uint32_t krow = (uint32_t)(pk * 16 + (lane & 15));
#pragma unroll
            for (int n = 0; n < 8; n++) {
                uint32_t off = (krow * KP + n * 8) * 2;
                uint32_t b0, b1;
                ldmx2t(b0, b1, v_b + off);
                mma16816(oacc[n], pa, b0, b1);
            }
        }
        __syncthreads();   // compute done before next prefetch overwrites buf^1
    }

    // ---- epilogue: normalize + store fp32 ----
    const float il = 1.0f / l_lo;
    const float ih = 1.0f / l_hi;
#pragma unroll
    for (int n = 0; n < 8; n++) {
        int c = n * 8 + qc * 2;
        float2 v0 = make_float2(oacc[n][0] * il, oacc[n][1] * il);
        float2 v1 = make_float2(oacc[n][2] * ih, oacc[n][3] * ih);
        *(float2*)&out[rlo * DHEAD + c] = v0;
        *(float2*)&out[rhi * DHEAD + c] = v1;
    }
}

// ===========================================================================
extern "C" void kernel_launch(void* const* d_in, const int* in_sizes, int n_in,
                              void* d_out, int out_size)
{
    const float* x  = (const float*)d_in[0];
    const float* Wq = (const float*)d_in[1];
    const float* bq = (const float*)d_in[2];
    const float* Wk = (const float*)d_in[3];
    const float* bk = (const float*)d_in[4];
    const float* Wv = (const float*)d_in[5];
    const float* bv = (const float*)d_in[6];
    float* out = (float*)d_out;

    (void)in_sizes; (void)n_in; (void)out_size;

    cudaFuncSetAttribute(qkv_kernel,
                         cudaFuncAttributeMaxDynamicSharedMemorySize, QKV_SMEM_BYTES);
    cudaFuncSetAttribute(attn_kernel,
                         cudaFuncAttributeMaxDynamicSharedMemorySize, ATTN_SMEM_BYTES);

    wsplit_kernel<<<192, 256>>>(Wq, Wk, Wv);
    qkv_kernel<<<dim3(BS_TOT / 64), 128, QKV_SMEM_BYTES>>>(x, bq, bk, bv);
    attn_kernel<<<dim3(SEQ / 128, BATCH), 256, ATTN_SMEM_BYTES>>>(out);
}